// round 5
// baseline (speedup 1.0000x reference)
#include <cuda_runtime.h>
#include <cstdint>

// ---------------- problem constants ----------------
#define M_TOK  8192      // 4 * 2048 tokens
#define DIN    4096
#define DOUT   4096
#define RRANK  64
#define NEXP   16
#define KAUG   1024      // NEXP * RRANK
#define KTOT   5120      // DIN + KAUG
#define SCALE_F 0.5f     // 32/64

// ---------------- scratch (static device globals; no allocation) ----------------
__device__ float g_H[M_TOK * RRANK];   // reservoir hidden  [8192,64]
__device__ float g_L[M_TOK * NEXP];    // router logits     [8192,16]
__device__ float g_G[M_TOK * KAUG];    // combine (x) hidden, scaled: [8192,1024]

// ============================================================================
// Kernel 1: hidden = x @ A^T, logits = x @ router^T
// 32 tokens x 80 outputs per block (64 A rows + 16 router rows), K=4096
// ============================================================================
__global__ __launch_bounds__(256) void k_hidden_logits(
    const float* __restrict__ x,
    const float* __restrict__ A,
    const float* __restrict__ Rw)
{
    __shared__ float Xs[32][33];
    __shared__ float Ws[80][33];
    const int tid = threadIdx.x;
    const int tx  = tid & 31;   // token in tile
    const int ty  = tid >> 5;   // 0..7 output phase
    const int tok0 = blockIdx.x * 32;

    float acc[10];
#pragma unroll
    for (int i = 0; i < 10; i++) acc[i] = 0.f;

    for (int k0 = 0; k0 < DIN; k0 += 32) {
#pragma unroll
        for (int i = 0; i < 4; i++) {           // X tile: 32x32
            int e = tid + i * 256;
            int r = e >> 5, c = e & 31;
            Xs[r][c] = x[(size_t)(tok0 + r) * DIN + k0 + c];
        }
#pragma unroll
        for (int i = 0; i < 10; i++) {          // W tile: 80x32
            int e = tid + i * 256;
            int r = e >> 5, c = e & 31;
            Ws[r][c] = (r < 64) ? A[(size_t)r * DIN + k0 + c]
                                : Rw[(size_t)(r - 64) * DIN + k0 + c];
        }
        __syncthreads();
#pragma unroll 8
        for (int kk = 0; kk < 32; kk++) {
            float xv = Xs[tx][kk];
#pragma unroll
            for (int o = 0; o < 10; o++)
                acc[o] += xv * Ws[ty + o * 8][kk];
        }
        __syncthreads();
    }
    const int tok = tok0 + tx;
#pragma unroll
    for (int o = 0; o < 10; o++) {
        int row = ty + o * 8;
        if (row < 64) g_H[tok * RRANK + row] = acc[o];
        else          g_L[tok * NEXP + (row - 64)] = acc[o];
    }
}

// ============================================================================
// Kernel 2: softmax(16) -> top2 -> renorm -> build G row (1024 floats)
// one warp per token
// ============================================================================
__global__ __launch_bounds__(256) void k_route()
{
    const int warp = (blockIdx.x * blockDim.x + threadIdx.x) >> 5;
    const int lane = threadIdx.x & 31;
    if (warp >= M_TOK) return;
    const int t = warp;
    const int le = lane & 15;

    float l = g_L[t * NEXP + le];

    // softmax over 16 (lanes 16..31 mirror 0..15; width-16 butterflies)
    float m = l;
#pragma unroll
    for (int s = 8; s >= 1; s >>= 1) m = fmaxf(m, __shfl_xor_sync(0xffffffffu, m, s, 16));
    float p = expf(l - m);
    float sum = p;
#pragma unroll
    for (int s = 8; s >= 1; s >>= 1) sum += __shfl_xor_sync(0xffffffffu, sum, s, 16);
    p /= sum;

    // top-1 (tie -> lowest index, matching lax.top_k)
    float v1 = p; int i1 = le;
#pragma unroll
    for (int s = 8; s >= 1; s >>= 1) {
        float ov = __shfl_xor_sync(0xffffffffu, v1, s, 16);
        int   oi = __shfl_xor_sync(0xffffffffu, i1, s, 16);
        if (ov > v1 || (ov == v1 && oi < i1)) { v1 = ov; i1 = oi; }
    }
    // top-2
    float v2 = (le == i1) ? -1e30f : p; int i2 = le;
#pragma unroll
    for (int s = 8; s >= 1; s >>= 1) {
        float ov = __shfl_xor_sync(0xffffffffu, v2, s, 16);
        int   oi = __shfl_xor_sync(0xffffffffu, i2, s, 16);
        if (ov > v2 || (ov == v2 && oi < i2)) { v2 = ov; i2 = oi; }
    }

    const float denom = v1 + v2 + 1e-6f;
    const float w1 = v1 / denom * SCALE_F;
    const float w2 = v2 / denom * SCALE_F;

    const float* h = g_H + (size_t)t * RRANK;
    float*       g = g_G + (size_t)t * KAUG;
#pragma unroll
    for (int j = 0; j < 32; j++) {
        int idx = j * 32 + lane;
        int e = idx >> 6, r = idx & 63;
        float v = 0.f;
        if (e == i1)      v = w1 * h[r];
        else if (e == i2) v = w2 * h[r];
        g[idx] = v;
    }
}

// ============================================================================
// Kernel 3: fused GEMM  out[8192,4096] = [x | G] @ [base_w | Bflat]^T + bias
// TF32 mma.sync m16n8k8, 128x128x32 tiles, cp.async double buffer
// ============================================================================
#define BM 128
#define BN 128
#define BK 32
#define STRD 36                      // BK + 4 pad (keeps 16B alignment, kills LDS conflicts)
#define KT_ITERS (KTOT / BK)         // 160

__device__ __forceinline__ void cp_async16(float* dst, const float* src) {
    uint32_t d = (uint32_t)__cvta_generic_to_shared(dst);
    asm volatile("cp.async.cg.shared.global [%0], [%1], 16;\n" :: "r"(d), "l"(src));
}
__device__ __forceinline__ uint32_t f2tf32(float f) {
    uint32_t r; asm("cvt.rna.tf32.f32 %0, %1;" : "=r"(r) : "f"(f)); return r;
}

__global__ __launch_bounds__(256, 2) void k_gemm(
    const float* __restrict__ x,
    const float* __restrict__ Wb,     // base_w [4096,4096]
    const float* __restrict__ bias,   // [4096]
    const float* __restrict__ Be,     // B [16,4096,64]
    float* __restrict__ out)
{
    extern __shared__ float smem[];
    // layout: A stages [2][BM*STRD], then B stages [2][BN*STRD]
    float* As[2] = { smem,                smem + BM * STRD };
    float* Bs[2] = { smem + 2 * BM * STRD, smem + 2 * BM * STRD + BN * STRD };

    const int tid   = threadIdx.x;
    const int warp  = tid >> 5;
    const int lane  = tid & 31;
    const int gId   = lane >> 2;     // 0..7
    const int tig   = lane & 3;      // 0..3
    const int warp_m = warp & 3;     // 4 warps along M -> 32 rows each
    const int warp_n = warp >> 2;    // 2 warps along N -> 64 cols each

    const int rowA0 = blockIdx.y * BM;     // token base
    const int rowB0 = blockIdx.x * BN;     // dout base

    auto load_stage = [&](int s, int kt) {
        const int k0 = kt * BK;
        // ---- A source: x or G ----
        const float* srcA; size_t strA;
        if (k0 < DIN) { srcA = x   + (size_t)rowA0 * DIN  + k0;         strA = DIN;  }
        else          { srcA = g_G + (size_t)rowA0 * KAUG + (k0 - DIN); strA = KAUG; }
        // ---- B source: base_w or Bflat (contiguous r-chunk inside one expert) ----
        const float* srcB; size_t strB;
        if (k0 < DIN) { srcB = Wb + (size_t)rowB0 * DIN + k0; strB = DIN; }
        else {
            int kb = k0 - DIN;
            srcB = Be + (size_t)(kb >> 6) * (DOUT * RRANK) + (size_t)rowB0 * RRANK + (kb & 63);
            strB = RRANK;
        }
        float* dA = As[s]; float* dB = Bs[s];
#pragma unroll
        for (int i = 0; i < 4; i++) {
            int e = tid + i * 256;         // 0..1023 chunks of 16B
            int r = e >> 3, c = (e & 7) * 4;
            cp_async16(dA + r * STRD + c, srcA + (size_t)r * strA + c);
        }
#pragma unroll
        for (int i = 0; i < 4; i++) {
            int e = tid + i * 256;
            int r = e >> 3, c = (e & 7) * 4;
            cp_async16(dB + r * STRD + c, srcB + (size_t)r * strB + c);
        }
        asm volatile("cp.async.commit_group;\n" ::);
    };

    float acc[2][8][4];
#pragma unroll
    for (int i = 0; i < 2; i++)
#pragma unroll
        for (int j = 0; j < 8; j++)
#pragma unroll
            for (int q = 0; q < 4; q++) acc[i][j][q] = 0.f;

    int s = 0;
    load_stage(0, 0);

    for (int kt = 0; kt < KT_ITERS; kt++) {
        if (kt + 1 < KT_ITERS) {
            load_stage(s ^ 1, kt + 1);
            asm volatile("cp.async.wait_group 1;\n" ::);
        } else {
            asm volatile("cp.async.wait_group 0;\n" ::);
        }
        __syncthreads();

        const float* As_ = As[s];
        const float* Bs_ = Bs[s];
#pragma unroll
        for (int kk = 0; kk < 4; kk++) {
            uint32_t afr[2][4];
#pragma unroll
            for (int i = 0; i < 2; i++) {
                int r0 = warp_m * 32 + i * 16 + gId;
                int kc = kk * 8 + tig;
                afr[i][0] = f2tf32(As_[r0 * STRD + kc]);
                afr[i][1] = f2tf32(As_[(r0 + 8) * STRD + kc]);
                afr[i][2] = f2tf32(As_[r0 * STRD + kc + 4]);
                afr[i][3] = f2tf32(As_[(r0 + 8) * STRD + kc + 4]);
            }
            uint32_t bfr[8][2];
#pragma unroll
            for (int j = 0; j < 8; j++) {
                int n0 = warp_n * 64 + j * 8 + gId;
                int kc = kk * 8 + tig;
                bfr[j][0] = f2tf32(Bs_[n0 * STRD + kc]);
                bfr[j][1] = f2tf32(Bs_[n0 * STRD + kc + 4]);
            }
#pragma unroll
            for (int i = 0; i < 2; i++)
#pragma unroll
                for (int j = 0; j < 8; j++) {
                    asm volatile(
                        "mma.sync.aligned.m16n8k8.row.col.f32.tf32.tf32.f32 "
                        "{%0,%1,%2,%3}, {%4,%5,%6,%7}, {%8,%9}, {%0,%1,%2,%3};\n"
                        : "+f"(acc[i][j][0]), "+f"(acc[i][j][1]),
                          "+f"(acc[i][j][2]), "+f"(acc[i][j][3])
                        : "r"(afr[i][0]), "r"(afr[i][1]), "r"(afr[i][2]), "r"(afr[i][3]),
                          "r"(bfr[j][0]), "r"(bfr[j][1]));
                }
        }
        __syncthreads();
        s ^= 1;
    }

    // epilogue: + bias, fp32 out, float2 stores
#pragma unroll
    for (int i = 0; i < 2; i++) {
        int rg0 = rowA0 + warp_m * 32 + i * 16 + gId;
#pragma unroll
        for (int j = 0; j < 8; j++) {
            int cg = rowB0 + warp_n * 64 + j * 8 + tig * 2;
            float2 bv = *(const float2*)&bias[cg];
            float2 v0 = { acc[i][j][0] + bv.x, acc[i][j][1] + bv.y };
            float2 v1 = { acc[i][j][2] + bv.x, acc[i][j][3] + bv.y };
            *(float2*)&out[(size_t)rg0 * DOUT + cg]       = v0;
            *(float2*)&out[(size_t)(rg0 + 8) * DOUT + cg] = v1;
        }
    }
}

// ============================================================================
// launch
// ============================================================================
extern "C" void kernel_launch(void* const* d_in, const int* in_sizes, int n_in,
                              void* d_out, int out_size)
{
    const float* x    = (const float*)d_in[0];   // [4,2048,4096]
    const float* Wb   = (const float*)d_in[1];   // [4096,4096]
    const float* bias = (const float*)d_in[2];   // [4096]
    const float* A    = (const float*)d_in[3];   // [64,4096]
    const float* Be   = (const float*)d_in[4];   // [16,4096,64]
    const float* Rw   = (const float*)d_in[5];   // [16,4096]
    float* out = (float*)d_out;

    // 1) hidden + logits
    k_hidden_logits<<<M_TOK / 32, 256>>>(x, A, Rw);

    // 2) routing + G build
    k_route<<<M_TOK / 8, 256>>>();

    // 3) fused GEMM (K = 5120 = Din + E*R)
    const int smem_bytes = (2 * BM * STRD + 2 * BN * STRD) * sizeof(float); // 73728
    cudaFuncSetAttribute(k_gemm, cudaFuncAttributeMaxDynamicSharedMemorySize, smem_bytes);
    dim3 grid(DOUT / BN, M_TOK / BM);   // (32, 64)
    k_gemm<<<grid, 256, smem_bytes>>>(x, Wb, bias, Be, out);
}

// round 7
// speedup vs baseline: 1.4060x; 1.4060x over previous
#include <cuda_runtime.h>
#include <cstdint>

// ---------------- problem constants ----------------
#define M_TOK  8192
#define DIN    4096
#define DOUT   4096
#define RRANK  64
#define NEXP   16
#define KAUG   1024
#define KTOT   5120
#define SCALE_F 0.5f

// ---------------- scratch (static device globals) ----------------
__device__ __align__(16) float g_H[M_TOK * RRANK];          // hidden        2MB
__device__ __align__(16) float g_G[M_TOK * KAUG];           // aug A-cols   32MB (tf32-rounded)
__device__ __align__(16) float g_Xr[M_TOK * DIN];           // x rounded   128MB
__device__ __align__(16) float g_Wr[(size_t)DOUT * DIN];    // W rounded    64MB
__device__ __align__(16) float g_Ber[NEXP * DOUT * RRANK];  // B rounded    16MB
__device__ __align__(16) float g_Ar[RRANK * DIN];           // A rounded     1MB

__device__ __forceinline__ float rna(float f) {
    uint32_t r; asm("cvt.rna.tf32.f32 %0, %1;" : "=r"(r) : "f"(f));
    return __uint_as_float(r);
}
__device__ __forceinline__ void cpa16(void* dst, const void* src) {
    uint32_t d = (uint32_t)__cvta_generic_to_shared(dst);
    asm volatile("cp.async.cg.shared.global [%0], [%1], 16;\n" :: "r"(d), "l"(src));
}
#define CP_COMMIT() asm volatile("cp.async.commit_group;\n" ::: "memory")
#define CP_WAIT(n)  asm volatile("cp.async.wait_group %0;\n" :: "n"(n) : "memory")

#define MMA_TF32(d0,d1,d2,d3,a0,a1,a2,a3,b0,b1) \
    asm volatile( \
        "mma.sync.aligned.m16n8k8.row.col.f32.tf32.tf32.f32 " \
        "{%0,%1,%2,%3}, {%4,%5,%6,%7}, {%8,%9}, {%0,%1,%2,%3};\n" \
        : "+f"(d0), "+f"(d1), "+f"(d2), "+f"(d3) \
        : "r"(a0), "r"(a1), "r"(a2), "r"(a3), "r"(b0), "r"(b1))

// ============================================================================
// Kernel 0: round x, W, B, A to tf32 once (RNA) into scratch
// ============================================================================
__global__ __launch_bounds__(256) void k_prep(
    const float* __restrict__ x, const float* __restrict__ Wb,
    const float* __restrict__ Be, const float* __restrict__ A)
{
    const long NX = (long)M_TOK * DIN / 4;
    const long NW = (long)DOUT * DIN / 4;
    const long NB = (long)NEXP * DOUT * RRANK / 4;
    const long NA = (long)RRANK * DIN / 4;
    const long total = NX + NW + NB + NA;
    for (long i = (long)blockIdx.x * blockDim.x + threadIdx.x; i < total;
         i += (long)gridDim.x * blockDim.x) {
        const float4* src; float4* dst; long j = i;
        if (j < NX)              { src = (const float4*)x;  dst = (float4*)g_Xr;  }
        else if ((j -= NX) < NW) { src = (const float4*)Wb; dst = (float4*)g_Wr;  }
        else if ((j -= NW) < NB) { src = (const float4*)Be; dst = (float4*)g_Ber; }
        else { j -= NB;            src = (const float4*)A;  dst = (float4*)g_Ar;  }
        float4 v = src[j];
        v.x = rna(v.x); v.y = rna(v.y); v.z = rna(v.z); v.w = rna(v.w);
        dst[j] = v;
    }
}

// ============================================================================
// Kernel 1: hidden = x @ A^T  via mma.sync tf32
// BM=64, BN=64, BK=32, 3-stage cp.async; 128 CTAs, 256 threads
// warp grid 2(M) x 4(N), warp tile 32x16
// ============================================================================
#define H_STRD 36
#define H_AF   (64 * H_STRD)    // floats per A stage
#define H_BF   (64 * H_STRD)
#define H_KT   (DIN / 32)       // 128

__global__ __launch_bounds__(256, 1) void k_hl()
{
    extern __shared__ float sm[];
    float* Asm = sm;                 // [3][H_AF]
    float* Bsm = sm + 3 * H_AF;      // [3][H_BF]

    const int tid = threadIdx.x, wid = tid >> 5, lane = tid & 31;
    const int gId = lane >> 2, tig = lane & 3;
    const int warp_m = wid & 1, warp_n = wid >> 1;
    const int rowA0 = blockIdx.x * 64;

    const int r0 = tid >> 3, c4 = (tid & 7) * 4;
    const float* pA0 = g_Xr + (size_t)(rowA0 + r0) * DIN + c4;
    const float* pB0 = g_Ar + (size_t)r0 * DIN + c4;
    const int sdst = r0 * H_STRD + c4;

    auto load_stage = [&](int kt) {
        const int s = kt % 3;
        const int k0 = kt * 32;
        float* dA = Asm + s * H_AF;
        float* dB = Bsm + s * H_BF;
#pragma unroll
        for (int i = 0; i < 2; i++)
            cpa16(dA + sdst + i * 32 * H_STRD, pA0 + k0 + (size_t)i * 32 * DIN);
#pragma unroll
        for (int i = 0; i < 2; i++)
            cpa16(dB + sdst + i * 32 * H_STRD, pB0 + k0 + (size_t)i * 32 * DIN);
        CP_COMMIT();
    };

    float acc[2][2][4];
#pragma unroll
    for (int a = 0; a < 2; a++)
#pragma unroll
        for (int b = 0; b < 2; b++)
#pragma unroll
            for (int q = 0; q < 4; q++) acc[a][b][q] = 0.f;

    load_stage(0); load_stage(1);

    for (int kt = 0; kt < H_KT; kt++) {
        if (kt + 2 < H_KT) load_stage(kt + 2);
        if (kt < H_KT - 2)      CP_WAIT(2);
        else if (kt == H_KT - 2) CP_WAIT(1);
        else                     CP_WAIT(0);
        __syncthreads();

        const float* As_ = Asm + (kt % 3) * H_AF;
        const float* Bs_ = Bsm + (kt % 3) * H_BF;
#pragma unroll
        for (int kk = 0; kk < 4; kk++) {
            const int kc = kk * 8 + tig;
            uint32_t af[2][4], bf[2][2];
#pragma unroll
            for (int mi = 0; mi < 2; mi++) {
                int rm = warp_m * 32 + mi * 16 + gId;
                af[mi][0] = __float_as_uint(As_[rm * H_STRD + kc]);
                af[mi][1] = __float_as_uint(As_[(rm + 8) * H_STRD + kc]);
                af[mi][2] = __float_as_uint(As_[rm * H_STRD + kc + 4]);
                af[mi][3] = __float_as_uint(As_[(rm + 8) * H_STRD + kc + 4]);
            }
#pragma unroll
            for (int ni = 0; ni < 2; ni++) {
                int rn = warp_n * 16 + ni * 8 + gId;
                bf[ni][0] = __float_as_uint(Bs_[rn * H_STRD + kc]);
                bf[ni][1] = __float_as_uint(Bs_[rn * H_STRD + kc + 4]);
            }
#pragma unroll
            for (int mi = 0; mi < 2; mi++)
#pragma unroll
                for (int ni = 0; ni < 2; ni++)
                    MMA_TF32(acc[mi][ni][0], acc[mi][ni][1], acc[mi][ni][2], acc[mi][ni][3],
                             af[mi][0], af[mi][1], af[mi][2], af[mi][3],
                             bf[ni][0], bf[ni][1]);
        }
        __syncthreads();
    }

#pragma unroll
    for (int mi = 0; mi < 2; mi++) {
        int rg = rowA0 + warp_m * 32 + mi * 16 + gId;
#pragma unroll
        for (int ni = 0; ni < 2; ni++) {
            int cg = warp_n * 16 + ni * 8 + tig * 2;
            *(float2*)&g_H[(size_t)rg * RRANK + cg] =
                make_float2(acc[mi][ni][0], acc[mi][ni][1]);
            *(float2*)&g_H[(size_t)(rg + 8) * RRANK + cg] =
                make_float2(acc[mi][ni][2], acc[mi][ni][3]);
        }
    }
}

// ============================================================================
// Kernel 2: fp32 logits (exact) + softmax + top2 + renorm + G build
// 4 tokens per warp; 256 blocks x 256 threads
// ============================================================================
__global__ __launch_bounds__(256) void k_route(
    const float* __restrict__ x, const float* __restrict__ Rw)
{
    const int warp = (blockIdx.x * blockDim.x + threadIdx.x) >> 5;
    const int lane = threadIdx.x & 31;
    const int t0 = warp * 4;
    if (t0 >= M_TOK) return;

    // ---- exact fp32 logits for 4 tokens ----
    float acc[4][NEXP];
#pragma unroll
    for (int q = 0; q < 4; q++)
#pragma unroll
        for (int e = 0; e < NEXP; e++) acc[q][e] = 0.f;

    for (int i = 0; i < 32; i++) {
        const int kidx = lane + i * 32;           // float4 index into a 4096 row
        float4 xv[4];
#pragma unroll
        for (int q = 0; q < 4; q++)
            xv[q] = *(const float4*)(x + (size_t)(t0 + q) * DIN + kidx * 4);
#pragma unroll
        for (int e = 0; e < NEXP; e++) {
            float4 wv = *(const float4*)(Rw + (size_t)e * DIN + kidx * 4);
#pragma unroll
            for (int q = 0; q < 4; q++)
                acc[q][e] += xv[q].x * wv.x + xv[q].y * wv.y +
                             xv[q].z * wv.z + xv[q].w * wv.w;
        }
    }
    // butterfly reduce across 32 lanes (all lanes end with full sums)
#pragma unroll
    for (int q = 0; q < 4; q++)
#pragma unroll
        for (int e = 0; e < NEXP; e++)
#pragma unroll
            for (int s = 16; s >= 1; s >>= 1)
                acc[q][e] += __shfl_xor_sync(0xffffffffu, acc[q][e], s);

    const int le = lane & 15;
#pragma unroll
    for (int q = 0; q < 4; q++) {
        const int t = t0 + q;
        float l = acc[q][le];

        float m = l;
#pragma unroll
        for (int s = 8; s >= 1; s >>= 1) m = fmaxf(m, __shfl_xor_sync(0xffffffffu, m, s, 16));
        float p = expf(l - m);
        float sum = p;
#pragma unroll
        for (int s = 8; s >= 1; s >>= 1) sum += __shfl_xor_sync(0xffffffffu, sum, s, 16);
        p /= sum;

        float v1 = p; int i1 = le;
#pragma unroll
        for (int s = 8; s >= 1; s >>= 1) {
            float ov = __shfl_xor_sync(0xffffffffu, v1, s, 16);
            int   oi = __shfl_xor_sync(0xffffffffu, i1, s, 16);
            if (ov > v1 || (ov == v1 && oi < i1)) { v1 = ov; i1 = oi; }
        }
        float v2 = (le == i1) ? -1e30f : p; int i2 = le;
#pragma unroll
        for (int s = 8; s >= 1; s >>= 1) {
            float ov = __shfl_xor_sync(0xffffffffu, v2, s, 16);
            int   oi = __shfl_xor_sync(0xffffffffu, i2, s, 16);
            if (ov > v2 || (ov == v2 && oi < i2)) { v2 = ov; i2 = oi; }
        }
        const float denom = v1 + v2 + 1e-6f;
        const float w1 = v1 / denom * SCALE_F;
        const float w2 = v2 / denom * SCALE_F;

        const float* h = g_H + (size_t)t * RRANK;
        float*       g = g_G + (size_t)t * KAUG;
#pragma unroll
        for (int j = 0; j < 32; j++) {
            int idx = j * 32 + lane;
            int e = idx >> 6, r = idx & 63;
            float v = 0.f;
            if (e == i1)      v = w1 * h[r];
            else if (e == i2) v = w2 * h[r];
            g[idx] = rna(v);     // tf32-rounded so GEMM needs no cvt
        }
    }
}

// ============================================================================
// Kernel 3: fused GEMM  out = [x | G] @ [W | Bflat]^T + bias   (tf32 mma.sync)
// BM=128, BN=256, BK=32, 3 stages; warp grid 2(M)x4(N), warp tile 64x64
// ============================================================================
#define G_STRD 36
#define G_AF   (128 * G_STRD)
#define G_BF   (256 * G_STRD)
#define G_KT   (KTOT / 32)      // 160
#define SMEM_G ((3 * (G_AF + G_BF)) * 4)   // 165,888 B
#define SMEM_H ((3 * (H_AF + H_BF)) * 4)   // 55,296 B

__global__ __launch_bounds__(256, 1) void k_gemm(
    const float* __restrict__ bias, float* __restrict__ out)
{
    extern __shared__ float sm[];
    float* Asm = sm;                 // [3][G_AF]
    float* Bsm = sm + 3 * G_AF;      // [3][G_BF]

    const int tid = threadIdx.x, wid = tid >> 5, lane = tid & 31;
    const int gId = lane >> 2, tig = lane & 3;
    const int warp_m = wid & 1, warp_n = wid >> 1;
    const int rowA0 = blockIdx.y * 128;
    const int rowB0 = blockIdx.x * 256;

    const int r0 = tid >> 3, c4 = (tid & 7) * 4;
    const float* pA0 = g_Xr + (size_t)(rowA0 + r0) * DIN  + c4;
    const float* pG0 = g_G  + (size_t)(rowA0 + r0) * KAUG + c4;
    const float* pW0 = g_Wr + (size_t)(rowB0 + r0) * DIN  + c4;
    const float* pE0 = g_Ber + (size_t)(rowB0 + r0) * RRANK + c4;
    const int sdst = r0 * G_STRD + c4;

    auto load_stage = [&](int kt) {
        const int s = kt % 3;
        const int k0 = kt * 32;
        float* dA = Asm + s * G_AF;
        float* dB = Bsm + s * G_BF;
        if (k0 < DIN) {
#pragma unroll
            for (int i = 0; i < 4; i++)
                cpa16(dA + sdst + i * 32 * G_STRD, pA0 + k0 + (size_t)i * 32 * DIN);
#pragma unroll
            for (int i = 0; i < 8; i++)
                cpa16(dB + sdst + i * 32 * G_STRD, pW0 + k0 + (size_t)i * 32 * DIN);
        } else {
            const int kb = k0 - DIN;
            const size_t eoff = (size_t)(kb >> 6) * ((size_t)DOUT * RRANK) + (kb & 63);
#pragma unroll
            for (int i = 0; i < 4; i++)
                cpa16(dA + sdst + i * 32 * G_STRD, pG0 + kb + (size_t)i * 32 * KAUG);
#pragma unroll
            for (int i = 0; i < 8; i++)
                cpa16(dB + sdst + i * 32 * G_STRD, pE0 + eoff + (size_t)i * 32 * RRANK);
        }
        CP_COMMIT();
    };

    float acc[4][8][4];
#pragma unroll
    for (int a = 0; a < 4; a++)
#pragma unroll
        for (int b = 0; b < 8; b++)
#pragma unroll
            for (int q = 0; q < 4; q++) acc[a][b][q] = 0.f;

    load_stage(0); load_stage(1);

    for (int kt = 0; kt < G_KT; kt++) {
        if (kt + 2 < G_KT) load_stage(kt + 2);
        if (kt < G_KT - 2)       CP_WAIT(2);
        else if (kt == G_KT - 2) CP_WAIT(1);
        else                     CP_WAIT(0);
        __syncthreads();

        const float* As_ = Asm + (kt % 3) * G_AF;
        const float* Bs_ = Bsm + (kt % 3) * G_BF;
#pragma unroll
        for (int kk = 0; kk < 4; kk++) {
            const int kc = kk * 8 + tig;
            uint32_t af[4][4], bf[8][2];
#pragma unroll
            for (int mi = 0; mi < 4; mi++) {
                int rm = warp_m * 64 + mi * 16 + gId;
                af[mi][0] = __float_as_uint(As_[rm * G_STRD + kc]);
                af[mi][1] = __float_as_uint(As_[(rm + 8) * G_STRD + kc]);
                af[mi][2] = __float_as_uint(As_[rm * G_STRD + kc + 4]);
                af[mi][3] = __float_as_uint(As_[(rm + 8) * G_STRD + kc + 4]);
            }
#pragma unroll
            for (int ni = 0; ni < 8; ni++) {
                int rn = warp_n * 64 + ni * 8 + gId;
                bf[ni][0] = __float_as_uint(Bs_[rn * G_STRD + kc]);
                bf[ni][1] = __float_as_uint(Bs_[rn * G_STRD + kc + 4]);
            }
#pragma unroll
            for (int mi = 0; mi < 4; mi++)
#pragma unroll
                for (int ni = 0; ni < 8; ni++)
                    MMA_TF32(acc[mi][ni][0], acc[mi][ni][1], acc[mi][ni][2], acc[mi][ni][3],
                             af[mi][0], af[mi][1], af[mi][2], af[mi][3],
                             bf[ni][0], bf[ni][1]);
        }
        __syncthreads();
    }

    // epilogue: + bias, float2 stores
#pragma unroll
    for (int mi = 0; mi < 4; mi++) {
        int rg = rowA0 + warp_m * 64 + mi * 16 + gId;
#pragma unroll
        for (int ni = 0; ni < 8; ni++) {
            int cg = rowB0 + warp_n * 64 + ni * 8 + tig * 2;
            float2 bv = *(const float2*)&bias[cg];
            *(float2*)&out[(size_t)rg * DOUT + cg] =
                make_float2(acc[mi][ni][0] + bv.x, acc[mi][ni][1] + bv.y);
            *(float2*)&out[(size_t)(rg + 8) * DOUT + cg] =
                make_float2(acc[mi][ni][2] + bv.x, acc[mi][ni][3] + bv.y);
        }
    }
}

// ============================================================================
// launch
// ============================================================================
extern "C" void kernel_launch(void* const* d_in, const int* in_sizes, int n_in,
                              void* d_out, int out_size)
{
    const float* x    = (const float*)d_in[0];   // [4,2048,4096]
    const float* Wb   = (const float*)d_in[1];   // [4096,4096]
    const float* bias = (const float*)d_in[2];   // [4096]
    const float* A    = (const float*)d_in[3];   // [64,4096]
    const float* Be   = (const float*)d_in[4];   // [16,4096,64]
    const float* Rw   = (const float*)d_in[5];   // [16,4096]
    float* out = (float*)d_out;

    cudaFuncSetAttribute(k_hl,   cudaFuncAttributeMaxDynamicSharedMemorySize, SMEM_H);
    cudaFuncSetAttribute(k_gemm, cudaFuncAttributeMaxDynamicSharedMemorySize, SMEM_G);

    k_prep<<<2048, 256>>>(x, Wb, Be, A);
    k_hl<<<M_TOK / 64, 256, SMEM_H>>>();
    k_route<<<M_TOK / 32, 256>>>(x, Rw);
    dim3 grid(DOUT / 256, M_TOK / 128);          // (16, 64)
    k_gemm<<<grid, 256, SMEM_G>>>(bias, out);
}

// round 8
// speedup vs baseline: 1.4217x; 1.0111x over previous
#include <cuda_runtime.h>
#include <cstdint>

// ---------------- problem constants ----------------
#define M_TOK  8192
#define DIN    4096
#define DOUT   4096
#define RRANK  64
#define NEXP   16
#define KAUG   1024
#define KTOT   5120
#define SCALE_F 0.5f

// ---------------- scratch (static device globals) ----------------
__device__ __align__(16) float g_H[M_TOK * RRANK];          // hidden        2MB
__device__ __align__(16) float g_G[M_TOK * KAUG];           // aug A-cols   32MB (tf32-rounded)
__device__ __align__(16) float g_Xr[M_TOK * DIN];           // x rounded   128MB
__device__ __align__(16) float g_Wr[(size_t)DOUT * DIN];    // W rounded    64MB
__device__ __align__(16) float g_Ber[NEXP * DOUT * RRANK];  // B rounded    16MB
__device__ __align__(16) float g_Ar[RRANK * DIN];           // A rounded     1MB

__device__ __forceinline__ float rna(float f) {
    uint32_t r; asm("cvt.rna.tf32.f32 %0, %1;" : "=r"(r) : "f"(f));
    return __uint_as_float(r);
}
__device__ __forceinline__ void cpa16(void* dst, const void* src) {
    uint32_t d = (uint32_t)__cvta_generic_to_shared(dst);
    asm volatile("cp.async.cg.shared.global [%0], [%1], 16;\n" :: "r"(d), "l"(src));
}
#define CP_COMMIT() asm volatile("cp.async.commit_group;\n" ::: "memory")
#define CP_WAIT(n)  asm volatile("cp.async.wait_group %0;\n" :: "n"(n) : "memory")

#define MMA_TF32(d0,d1,d2,d3,a0,a1,a2,a3,b0,b1) \
    asm volatile( \
        "mma.sync.aligned.m16n8k8.row.col.f32.tf32.tf32.f32 " \
        "{%0,%1,%2,%3}, {%4,%5,%6,%7}, {%8,%9}, {%0,%1,%2,%3};\n" \
        : "+f"(d0), "+f"(d1), "+f"(d2), "+f"(d3) \
        : "r"(a0), "r"(a1), "r"(a2), "r"(a3), "r"(b0), "r"(b1))

// ============================================================================
// Kernel 0: round x, W, B, A to tf32 once (RNA) into scratch
// ============================================================================
__global__ __launch_bounds__(256) void k_prep(
    const float* __restrict__ x, const float* __restrict__ Wb,
    const float* __restrict__ Be, const float* __restrict__ A)
{
    const long NX = (long)M_TOK * DIN / 4;
    const long NW = (long)DOUT * DIN / 4;
    const long NB = (long)NEXP * DOUT * RRANK / 4;
    const long NA = (long)RRANK * DIN / 4;
    const long total = NX + NW + NB + NA;
    for (long i = (long)blockIdx.x * blockDim.x + threadIdx.x; i < total;
         i += (long)gridDim.x * blockDim.x) {
        const float4* src; float4* dst; long j = i;
        if (j < NX)              { src = (const float4*)x;  dst = (float4*)g_Xr;  }
        else if ((j -= NX) < NW) { src = (const float4*)Wb; dst = (float4*)g_Wr;  }
        else if ((j -= NW) < NB) { src = (const float4*)Be; dst = (float4*)g_Ber; }
        else { j -= NB;            src = (const float4*)A;  dst = (float4*)g_Ar;  }
        float4 v = src[j];
        v.x = rna(v.x); v.y = rna(v.y); v.z = rna(v.z); v.w = rna(v.w);
        dst[j] = v;
    }
}

// ============================================================================
// Kernel 1: hidden = x @ A^T via mma.sync tf32
// BM=64, BN=64, BK=32, 3 stages, ONE barrier per k-iter (loads issued
// after the barrier -> overlap with MMA; write buf (kt-1)%3 provably drained)
// ============================================================================
#define H_STRD 36
#define H_AF   (64 * H_STRD)
#define H_BF   (64 * H_STRD)
#define H_KT   (DIN / 32)       // 128
#define SMEM_H ((3 * (H_AF + H_BF)) * 4)

__global__ __launch_bounds__(256, 1) void k_hl()
{
    extern __shared__ float sm[];
    float* Asm = sm;
    float* Bsm = sm + 3 * H_AF;

    const int tid = threadIdx.x, wid = tid >> 5, lane = tid & 31;
    const int gId = lane >> 2, tig = lane & 3;
    const int warp_m = wid & 1, warp_n = wid >> 1;
    const int rowA0 = blockIdx.x * 64;

    const int r0 = tid >> 3, c4 = (tid & 7) * 4;
    const float* pA0 = g_Xr + (size_t)(rowA0 + r0) * DIN + c4;
    const float* pB0 = g_Ar + (size_t)r0 * DIN + c4;
    const int sdst = r0 * H_STRD + c4;

    auto load_stage = [&](int kt) {
        const int s = kt % 3;
        const int k0 = kt * 32;
        float* dA = Asm + s * H_AF;
        float* dB = Bsm + s * H_BF;
#pragma unroll
        for (int i = 0; i < 2; i++)
            cpa16(dA + sdst + i * 32 * H_STRD, pA0 + k0 + (size_t)i * 32 * DIN);
#pragma unroll
        for (int i = 0; i < 2; i++)
            cpa16(dB + sdst + i * 32 * H_STRD, pB0 + k0 + (size_t)i * 32 * DIN);
        CP_COMMIT();
    };

    float acc[2][2][4];
#pragma unroll
    for (int a = 0; a < 2; a++)
#pragma unroll
        for (int b = 0; b < 2; b++)
#pragma unroll
            for (int q = 0; q < 4; q++) acc[a][b][q] = 0.f;

    load_stage(0); load_stage(1);

    for (int kt = 0; kt < H_KT; kt++) {
        if (kt < H_KT - 1) CP_WAIT(1); else CP_WAIT(0);
        __syncthreads();
        if (kt + 2 < H_KT) load_stage(kt + 2);

        const float* As_ = Asm + (kt % 3) * H_AF;
        const float* Bs_ = Bsm + (kt % 3) * H_BF;
#pragma unroll
        for (int kk = 0; kk < 4; kk++) {
            const int kc = kk * 8 + tig;
            uint32_t af[2][4], bf[2][2];
#pragma unroll
            for (int mi = 0; mi < 2; mi++) {
                int rm = warp_m * 32 + mi * 16 + gId;
                af[mi][0] = __float_as_uint(As_[rm * H_STRD + kc]);
                af[mi][1] = __float_as_uint(As_[(rm + 8) * H_STRD + kc]);
                af[mi][2] = __float_as_uint(As_[rm * H_STRD + kc + 4]);
                af[mi][3] = __float_as_uint(As_[(rm + 8) * H_STRD + kc + 4]);
            }
#pragma unroll
            for (int ni = 0; ni < 2; ni++) {
                int rn = warp_n * 16 + ni * 8 + gId;
                bf[ni][0] = __float_as_uint(Bs_[rn * H_STRD + kc]);
                bf[ni][1] = __float_as_uint(Bs_[rn * H_STRD + kc + 4]);
            }
#pragma unroll
            for (int mi = 0; mi < 2; mi++)
#pragma unroll
                for (int ni = 0; ni < 2; ni++)
                    MMA_TF32(acc[mi][ni][0], acc[mi][ni][1], acc[mi][ni][2], acc[mi][ni][3],
                             af[mi][0], af[mi][1], af[mi][2], af[mi][3],
                             bf[ni][0], bf[ni][1]);
        }
    }

#pragma unroll
    for (int mi = 0; mi < 2; mi++) {
        int rg = rowA0 + warp_m * 32 + mi * 16 + gId;
#pragma unroll
        for (int ni = 0; ni < 2; ni++) {
            int cg = warp_n * 16 + ni * 8 + tig * 2;
            *(float2*)&g_H[(size_t)rg * RRANK + cg] =
                make_float2(acc[mi][ni][0], acc[mi][ni][1]);
            *(float2*)&g_H[(size_t)(rg + 8) * RRANK + cg] =
                make_float2(acc[mi][ni][2], acc[mi][ni][3]);
        }
    }
}

// ============================================================================
// Kernel 2: fp32 logits (exact) + softmax + top2 + renorm + G build
// ============================================================================
__global__ __launch_bounds__(256) void k_route(
    const float* __restrict__ x, const float* __restrict__ Rw)
{
    const int warp = (blockIdx.x * blockDim.x + threadIdx.x) >> 5;
    const int lane = threadIdx.x & 31;
    const int t0 = warp * 4;
    if (t0 >= M_TOK) return;

    float acc[4][NEXP];
#pragma unroll
    for (int q = 0; q < 4; q++)
#pragma unroll
        for (int e = 0; e < NEXP; e++) acc[q][e] = 0.f;

    for (int i = 0; i < 32; i++) {
        const int kidx = lane + i * 32;
        float4 xv[4];
#pragma unroll
        for (int q = 0; q < 4; q++)
            xv[q] = *(const float4*)(x + (size_t)(t0 + q) * DIN + kidx * 4);
#pragma unroll
        for (int e = 0; e < NEXP; e++) {
            float4 wv = *(const float4*)(Rw + (size_t)e * DIN + kidx * 4);
#pragma unroll
            for (int q = 0; q < 4; q++)
                acc[q][e] += xv[q].x * wv.x + xv[q].y * wv.y +
                             xv[q].z * wv.z + xv[q].w * wv.w;
        }
    }
#pragma unroll
    for (int q = 0; q < 4; q++)
#pragma unroll
        for (int e = 0; e < NEXP; e++)
#pragma unroll
            for (int s = 16; s >= 1; s >>= 1)
                acc[q][e] += __shfl_xor_sync(0xffffffffu, acc[q][e], s);

    const int le = lane & 15;
#pragma unroll
    for (int q = 0; q < 4; q++) {
        const int t = t0 + q;
        float l = acc[q][le];

        float m = l;
#pragma unroll
        for (int s = 8; s >= 1; s >>= 1) m = fmaxf(m, __shfl_xor_sync(0xffffffffu, m, s, 16));
        float p = expf(l - m);
        float sum = p;
#pragma unroll
        for (int s = 8; s >= 1; s >>= 1) sum += __shfl_xor_sync(0xffffffffu, sum, s, 16);
        p /= sum;

        float v1 = p; int i1 = le;
#pragma unroll
        for (int s = 8; s >= 1; s >>= 1) {
            float ov = __shfl_xor_sync(0xffffffffu, v1, s, 16);
            int   oi = __shfl_xor_sync(0xffffffffu, i1, s, 16);
            if (ov > v1 || (ov == v1 && oi < i1)) { v1 = ov; i1 = oi; }
        }
        float v2 = (le == i1) ? -1e30f : p; int i2 = le;
#pragma unroll
        for (int s = 8; s >= 1; s >>= 1) {
            float ov = __shfl_xor_sync(0xffffffffu, v2, s, 16);
            int   oi = __shfl_xor_sync(0xffffffffu, i2, s, 16);
            if (ov > v2 || (ov == v2 && oi < i2)) { v2 = ov; i2 = oi; }
        }
        const float denom = v1 + v2 + 1e-6f;
        const float w1 = v1 / denom * SCALE_F;
        const float w2 = v2 / denom * SCALE_F;

        const float* h = g_H + (size_t)t * RRANK;
        float*       g = g_G + (size_t)t * KAUG;
#pragma unroll
        for (int j = 0; j < 32; j++) {
            int idx = j * 32 + lane;
            int e = idx >> 6, r = idx & 63;
            float v = 0.f;
            if (e == i1)      v = w1 * h[r];
            else if (e == i2) v = w2 * h[r];
            g[idx] = rna(v);
        }
    }
}

// ============================================================================
// Kernel 3: fused GEMM  out = [x | G] @ [W | Bflat]^T + bias   (tf32 mma.sync)
// BM=128, BN=256, BK=32, 4 stages, ONE barrier per k-iter, loads after sync
// ============================================================================
#define G_STRD 36
#define G_AF   (128 * G_STRD)
#define G_BF   (256 * G_STRD)
#define G_KT   (KTOT / 32)      // 160
#define G_NS   4
#define SMEM_G ((G_NS * (G_AF + G_BF)) * 4)   // 221,184 B

__global__ __launch_bounds__(256, 1) void k_gemm(
    const float* __restrict__ bias, float* __restrict__ out)
{
    extern __shared__ float sm[];
    float* Asm = sm;                     // [4][G_AF]
    float* Bsm = sm + G_NS * G_AF;       // [4][G_BF]

    const int tid = threadIdx.x, wid = tid >> 5, lane = tid & 31;
    const int gId = lane >> 2, tig = lane & 3;
    const int warp_m = wid & 1, warp_n = wid >> 1;
    const int rowA0 = blockIdx.y * 128;
    const int rowB0 = blockIdx.x * 256;

    const int r0 = tid >> 3, c4 = (tid & 7) * 4;
    const float* pA0 = g_Xr + (size_t)(rowA0 + r0) * DIN  + c4;
    const float* pG0 = g_G  + (size_t)(rowA0 + r0) * KAUG + c4;
    const float* pW0 = g_Wr + (size_t)(rowB0 + r0) * DIN  + c4;
    const float* pE0 = g_Ber + (size_t)(rowB0 + r0) * RRANK + c4;
    const int sdst = r0 * G_STRD + c4;

    auto load_stage = [&](int kt) {
        const int s = kt & (G_NS - 1);
        const int k0 = kt * 32;
        float* dA = Asm + s * G_AF;
        float* dB = Bsm + s * G_BF;
        if (k0 < DIN) {
#pragma unroll
            for (int i = 0; i < 4; i++)
                cpa16(dA + sdst + i * 32 * G_STRD, pA0 + k0 + (size_t)i * 32 * DIN);
#pragma unroll
            for (int i = 0; i < 8; i++)
                cpa16(dB + sdst + i * 32 * G_STRD, pW0 + k0 + (size_t)i * 32 * DIN);
        } else {
            const int kb = k0 - DIN;
            const size_t eoff = (size_t)(kb >> 6) * ((size_t)DOUT * RRANK) + (kb & 63);
#pragma unroll
            for (int i = 0; i < 4; i++)
                cpa16(dA + sdst + i * 32 * G_STRD, pG0 + kb + (size_t)i * 32 * KAUG);
#pragma unroll
            for (int i = 0; i < 8; i++)
                cpa16(dB + sdst + i * 32 * G_STRD, pE0 + eoff + (size_t)i * 32 * RRANK);
        }
        CP_COMMIT();
    };

    float acc[4][8][4];
#pragma unroll
    for (int a = 0; a < 4; a++)
#pragma unroll
        for (int b = 0; b < 8; b++)
#pragma unroll
            for (int q = 0; q < 4; q++) acc[a][b][q] = 0.f;

    load_stage(0); load_stage(1); load_stage(2);

    for (int kt = 0; kt < G_KT; kt++) {
        // pending groups entering iter kt: {kt, kt+1, kt+2}; drain to stage kt
        if (kt <= G_KT - 3)      CP_WAIT(2);
        else if (kt == G_KT - 2) CP_WAIT(1);
        else                     CP_WAIT(0);
        __syncthreads();
        // write buf (kt+3)%4 == (kt-1)%4: all warps finished compute(kt-1)
        if (kt + 3 < G_KT) load_stage(kt + 3);

        const float* As_ = Asm + (kt & (G_NS - 1)) * G_AF;
        const float* Bs_ = Bsm + (kt & (G_NS - 1)) * G_BF;
#pragma unroll
        for (int kk = 0; kk < 4; kk++) {
            const int kc = kk * 8 + tig;
            uint32_t af[4][4], bf[8][2];
#pragma unroll
            for (int mi = 0; mi < 4; mi++) {
                int rm = warp_m * 64 + mi * 16 + gId;
                af[mi][0] = __float_as_uint(As_[rm * G_STRD + kc]);
                af[mi][1] = __float_as_uint(As_[(rm + 8) * G_STRD + kc]);
                af[mi][2] = __float_as_uint(As_[rm * G_STRD + kc + 4]);
                af[mi][3] = __float_as_uint(As_[(rm + 8) * G_STRD + kc + 4]);
            }
#pragma unroll
            for (int ni = 0; ni < 8; ni++) {
                int rn = warp_n * 64 + ni * 8 + gId;
                bf[ni][0] = __float_as_uint(Bs_[rn * G_STRD + kc]);
                bf[ni][1] = __float_as_uint(Bs_[rn * G_STRD + kc + 4]);
            }
#pragma unroll
            for (int mi = 0; mi < 4; mi++)
#pragma unroll
                for (int ni = 0; ni < 8; ni++)
                    MMA_TF32(acc[mi][ni][0], acc[mi][ni][1], acc[mi][ni][2], acc[mi][ni][3],
                             af[mi][0], af[mi][1], af[mi][2], af[mi][3],
                             bf[ni][0], bf[ni][1]);
        }
    }

    // epilogue: + bias, float2 stores
#pragma unroll
    for (int mi = 0; mi < 4; mi++) {
        int rg = rowA0 + warp_m * 64 + mi * 16 + gId;
#pragma unroll
        for (int ni = 0; ni < 8; ni++) {
            int cg = rowB0 + warp_n * 64 + ni * 8 + tig * 2;
            float2 bv = *(const float2*)&bias[cg];
            *(float2*)&out[(size_t)rg * DOUT + cg] =
                make_float2(acc[mi][ni][0] + bv.x, acc[mi][ni][1] + bv.y);
            *(float2*)&out[(size_t)(rg + 8) * DOUT + cg] =
                make_float2(acc[mi][ni][2] + bv.x, acc[mi][ni][3] + bv.y);
        }
    }
}

// ============================================================================
// launch
// ============================================================================
extern "C" void kernel_launch(void* const* d_in, const int* in_sizes, int n_in,
                              void* d_out, int out_size)
{
    const float* x    = (const float*)d_in[0];
    const float* Wb   = (const float*)d_in[1];
    const float* bias = (const float*)d_in[2];
    const float* A    = (const float*)d_in[3];
    const float* Be   = (const float*)d_in[4];
    const float* Rw   = (const float*)d_in[5];
    float* out = (float*)d_out;

    cudaFuncSetAttribute(k_hl,   cudaFuncAttributeMaxDynamicSharedMemorySize, SMEM_H);
    cudaFuncSetAttribute(k_gemm, cudaFuncAttributeMaxDynamicSharedMemorySize, SMEM_G);

    k_prep<<<2048, 256>>>(x, Wb, Be, A);
    k_hl<<<M_TOK / 64, 256, SMEM_H>>>();
    k_route<<<M_TOK / 32, 256>>>(x, Rw);
    dim3 grid(DOUT / 256, M_TOK / 128);          // (16, 64)
    k_gemm<<<grid, 256, SMEM_G>>>(bias, out);
}

// round 14
// speedup vs baseline: 1.4882x; 1.0468x over previous
#include <cuda_runtime.h>
#include <cstdint>

// ---------------- problem constants ----------------
#define M_TOK  8192
#define DIN    4096
#define DOUT   4096
#define RRANK  64
#define NEXP   16
#define KAUG   1024
#define KTOT   5120
#define SCALE_F 0.5f

// ---------------- scratch (static device globals) ----------------
// All K-bearing arrays are stored k-PERMUTED: within each 8-wide k-group,
// logical t -> physical (t<4 ? 2t : 2(t-4)+1). GEMM sum over k is invariant.
__device__ __align__(16) float g_H[M_TOK * RRANK];          // hidden (r-order, unpermuted)
__device__ __align__(16) float g_G[M_TOK * KAUG];           // aug A-cols, tf32 + k-permuted
__device__ __align__(16) float g_Xr[M_TOK * DIN];           // x  tf32 + k-permuted
__device__ __align__(16) float g_Wr[(size_t)DOUT * DIN];    // W  tf32 + k-permuted
__device__ __align__(16) float g_Ber[NEXP * DOUT * RRANK];  // B  tf32 + r-permuted
__device__ __align__(16) float g_Ar[RRANK * DIN];           // A  tf32 + k-permuted

__device__ __forceinline__ float rna(float f) {
    uint32_t r; asm("cvt.rna.tf32.f32 %0, %1;" : "=r"(r) : "f"(f));
    return __uint_as_float(r);
}
__device__ __forceinline__ void cpa16(void* dst, const void* src) {
    uint32_t d = (uint32_t)__cvta_generic_to_shared(dst);
    asm volatile("cp.async.cg.shared.global [%0], [%1], 16;\n" :: "r"(d), "l"(src));
}
#define CP_COMMIT() asm volatile("cp.async.commit_group;\n" ::: "memory")
#define CP_WAIT(n)  asm volatile("cp.async.wait_group %0;\n" :: "n"(n) : "memory")

#define MMA_TF32(d0,d1,d2,d3,a0,a1,a2,a3,b0,b1) \
    asm volatile( \
        "mma.sync.aligned.m16n8k8.row.col.f32.tf32.tf32.f32 " \
        "{%0,%1,%2,%3}, {%4,%5,%6,%7}, {%8,%9}, {%0,%1,%2,%3};\n" \
        : "+f"(d0), "+f"(d1), "+f"(d2), "+f"(d3) \
        : "r"(a0), "r"(a1), "r"(a2), "r"(a3), "r"(b0), "r"(b1))

// ============================================================================
// Kernel 0: round to tf32 (RNA) AND apply the 8-group k-permutation.
// A float4 at 4-aligned k covers one half of an 8-group: low half (k%8==0)
// lands at phys {0,2,4,6}+base, high half (k%8==4) at {1,3,5,7}+base.
// ============================================================================
__global__ __launch_bounds__(256) void k_prep(
    const float* __restrict__ x, const float* __restrict__ Wb,
    const float* __restrict__ Be, const float* __restrict__ A)
{
    const long NX = (long)M_TOK * DIN / 4;
    const long NW = (long)DOUT * DIN / 4;
    const long NB = (long)NEXP * DOUT * RRANK / 4;
    const long NA = (long)RRANK * DIN / 4;
    const long total = NX + NW + NB + NA;
    for (long i = (long)blockIdx.x * blockDim.x + threadIdx.x; i < total;
         i += (long)gridDim.x * blockDim.x) {
        const float4* src; float* dst; long j = i; int kmask;
        if (j < NX)              { src = (const float4*)x;  dst = g_Xr;  kmask = DIN - 1;   }
        else if ((j -= NX) < NW) { src = (const float4*)Wb; dst = g_Wr;  kmask = DIN - 1;   }
        else if ((j -= NW) < NB) { src = (const float4*)Be; dst = g_Ber; kmask = RRANK - 1; }
        else { j -= NB;            src = (const float4*)A;  dst = g_Ar;  kmask = DIN - 1;   }
        float4 v = src[j];
        const long e0 = 4 * j;                 // flat element index
        const int  k0 = (int)(e0 & kmask);     // k position (4-aligned)
        const long rowbase = e0 - k0;
        const int  kb = k0 & ~7;
        const int  hi = (k0 >> 2) & 1;         // 0: low half, 1: high half
        dst[rowbase + kb + hi + 0] = rna(v.x);
        dst[rowbase + kb + hi + 2] = rna(v.y);
        dst[rowbase + kb + hi + 4] = rna(v.z);
        dst[rowbase + kb + hi + 6] = rna(v.w);
    }
}

// ============================================================================
// Kernel 1: hidden = x @ A^T (both operands k-permuted -> float2 fragments)
// BM=64, BN=64, BK=32, 3 stages, 256 threads, warp tile 32x16
// ============================================================================
#define H_STRD 40
#define H_AF   (64 * H_STRD)
#define H_BF   (64 * H_STRD)
#define H_KT   (DIN / 32)       // 128
#define SMEM_H ((3 * (H_AF + H_BF)) * 4)   // 61,440 B

__global__ __launch_bounds__(256, 1) void k_hl()
{
    extern __shared__ float sm[];
    float* Asm = sm;
    float* Bsm = sm + 3 * H_AF;

    const int tid = threadIdx.x, wid = tid >> 5, lane = tid & 31;
    const int gId = lane >> 2, tig = lane & 3;
    const int warp_m = wid & 1, warp_n = wid >> 1;
    const int rowA0 = blockIdx.x * 64;

    const int r0 = tid >> 3, c4 = (tid & 7) * 4;   // r0: 0..31
    const float* pA0 = g_Xr + (size_t)(rowA0 + r0) * DIN + c4;
    const float* pB0 = g_Ar + (size_t)r0 * DIN + c4;
    const int sdst = r0 * H_STRD + c4;

    auto load_stage = [&](int kt) {
        const int s = kt % 3;
        const int k0 = kt * 32;
        float* dA = Asm + s * H_AF;
        float* dB = Bsm + s * H_BF;
#pragma unroll
        for (int i = 0; i < 2; i++)
            cpa16(dA + sdst + i * 32 * H_STRD, pA0 + k0 + (size_t)i * 32 * DIN);
#pragma unroll
        for (int i = 0; i < 2; i++)
            cpa16(dB + sdst + i * 32 * H_STRD, pB0 + k0 + (size_t)i * 32 * DIN);
        CP_COMMIT();
    };

    float acc[2][2][4];
#pragma unroll
    for (int a = 0; a < 2; a++)
#pragma unroll
        for (int b = 0; b < 2; b++)
#pragma unroll
            for (int q = 0; q < 4; q++) acc[a][b][q] = 0.f;

    load_stage(0); load_stage(1);

    for (int kt = 0; kt < H_KT; kt++) {
        if (kt < H_KT - 1) CP_WAIT(1); else CP_WAIT(0);
        __syncthreads();
        if (kt + 2 < H_KT) load_stage(kt + 2);

        const float* As_ = Asm + (kt % 3) * H_AF;
        const float* Bs_ = Bsm + (kt % 3) * H_BF;
#pragma unroll
        for (int kk = 0; kk < 4; kk++) {
            const int kc = kk * 8 + tig * 2;   // permuted: (tig, tig+4) adjacent
            float2 afl[2][2]; float2 bfl[2];
#pragma unroll
            for (int mi = 0; mi < 2; mi++) {
                int rm = warp_m * 32 + mi * 16 + gId;
                afl[mi][0] = *(const float2*)&As_[rm * H_STRD + kc];
                afl[mi][1] = *(const float2*)&As_[(rm + 8) * H_STRD + kc];
            }
#pragma unroll
            for (int ni = 0; ni < 2; ni++) {
                int rn = warp_n * 16 + ni * 8 + gId;
                bfl[ni] = *(const float2*)&Bs_[rn * H_STRD + kc];
            }
#pragma unroll
            for (int mi = 0; mi < 2; mi++)
#pragma unroll
                for (int ni = 0; ni < 2; ni++)
                    MMA_TF32(acc[mi][ni][0], acc[mi][ni][1], acc[mi][ni][2], acc[mi][ni][3],
                             __float_as_uint(afl[mi][0].x), __float_as_uint(afl[mi][1].x),
                             __float_as_uint(afl[mi][0].y), __float_as_uint(afl[mi][1].y),
                             __float_as_uint(bfl[ni].x),    __float_as_uint(bfl[ni].y));
        }
    }

#pragma unroll
    for (int mi = 0; mi < 2; mi++) {
        int rg = rowA0 + warp_m * 32 + mi * 16 + gId;
#pragma unroll
        for (int ni = 0; ni < 2; ni++) {
            int cg = warp_n * 16 + ni * 8 + tig * 2;
            *(float2*)&g_H[(size_t)rg * RRANK + cg] =
                make_float2(acc[mi][ni][0], acc[mi][ni][1]);
            *(float2*)&g_H[(size_t)(rg + 8) * RRANK + cg] =
                make_float2(acc[mi][ni][2], acc[mi][ni][3]);
        }
    }
}

// ============================================================================
// Kernel 2: fp32 logits (exact) + softmax + top2 + renorm + G build
// G is written tf32-rounded AND k-permuted (matching g_Ber's r-permutation)
// ============================================================================
__global__ __launch_bounds__(256) void k_route(
    const float* __restrict__ x, const float* __restrict__ Rw)
{
    const int warp = (blockIdx.x * blockDim.x + threadIdx.x) >> 5;
    const int lane = threadIdx.x & 31;
    const int t0 = warp * 4;
    if (t0 >= M_TOK) return;

    float acc[4][NEXP];
#pragma unroll
    for (int q = 0; q < 4; q++)
#pragma unroll
        for (int e = 0; e < NEXP; e++) acc[q][e] = 0.f;

    for (int i = 0; i < 32; i++) {
        const int kidx = lane + i * 32;
        float4 xv[4];
#pragma unroll
        for (int q = 0; q < 4; q++)
            xv[q] = *(const float4*)(x + (size_t)(t0 + q) * DIN + kidx * 4);
#pragma unroll
        for (int e = 0; e < NEXP; e++) {
            float4 wv = *(const float4*)(Rw + (size_t)e * DIN + kidx * 4);
#pragma unroll
            for (int q = 0; q < 4; q++)
                acc[q][e] += xv[q].x * wv.x + xv[q].y * wv.y +
                             xv[q].z * wv.z + xv[q].w * wv.w;
        }
    }
#pragma unroll
    for (int q = 0; q < 4; q++)
#pragma unroll
        for (int e = 0; e < NEXP; e++)
#pragma unroll
            for (int s = 16; s >= 1; s >>= 1)
                acc[q][e] += __shfl_xor_sync(0xffffffffu, acc[q][e], s);

    const int le = lane & 15;
#pragma unroll
    for (int q = 0; q < 4; q++) {
        const int t = t0 + q;
        float l = acc[q][le];

        float m = l;
#pragma unroll
        for (int s = 8; s >= 1; s >>= 1) m = fmaxf(m, __shfl_xor_sync(0xffffffffu, m, s, 16));
        float p = expf(l - m);
        float sum = p;
#pragma unroll
        for (int s = 8; s >= 1; s >>= 1) sum += __shfl_xor_sync(0xffffffffu, sum, s, 16);
        p /= sum;

        float v1 = p; int i1 = le;
#pragma unroll
        for (int s = 8; s >= 1; s >>= 1) {
            float ov = __shfl_xor_sync(0xffffffffu, v1, s, 16);
            int   oi = __shfl_xor_sync(0xffffffffu, i1, s, 16);
            if (ov > v1 || (ov == v1 && oi < i1)) { v1 = ov; i1 = oi; }
        }
        float v2 = (le == i1) ? -1e30f : p; int i2 = le;
#pragma unroll
        for (int s = 8; s >= 1; s >>= 1) {
            float ov = __shfl_xor_sync(0xffffffffu, v2, s, 16);
            int   oi = __shfl_xor_sync(0xffffffffu, i2, s, 16);
            if (ov > v2 || (ov == v2 && oi < i2)) { v2 = ov; i2 = oi; }
        }
        const float denom = v1 + v2 + 1e-6f;
        const float w1 = v1 / denom * SCALE_F;
        const float w2 = v2 / denom * SCALE_F;

        const float* h = g_H + (size_t)t * RRANK;
        float*       g = g_G + (size_t)t * KAUG;
#pragma unroll
        for (int j = 0; j < 32; j++) {
            int idx = j * 32 + lane;
            int e = idx >> 6, r = idx & 63;
            float v = 0.f;
            if (e == i1)      v = w1 * h[r];
            else if (e == i2) v = w2 * h[r];
            // permuted store: within 8-group, t -> (t<4 ? 2t : 2(t-4)+1)
            int ph = (idx & ~7) | (((idx & 3) << 1) | ((idx >> 2) & 1));
            g[ph] = rna(v);
        }
    }
}

// ============================================================================
// Kernel 3: fused GEMM  out = [x | G] @ [W | Bflat]^T + bias   (tf32 mma.sync)
// 512 threads (16 warps), BM=128, BN=256, BK=32, 3 stages, warp tile 64x32
// k-permuted operands -> all fragment loads are LDS.64, conflict-free @STRD=40
// ============================================================================
#define G_STRD 40
#define G_AF   (128 * G_STRD)
#define G_BF   (256 * G_STRD)
#define G_KT   (KTOT / 32)      // 160
#define G_NS   3
#define SMEM_G ((G_NS * (G_AF + G_BF)) * 4)   // 184,320 B

__global__ __launch_bounds__(512, 1) void k_gemm(
    const float* __restrict__ bias, float* __restrict__ out)
{
    extern __shared__ float sm[];
    float* Asm = sm;                     // [3][G_AF]
    float* Bsm = sm + G_NS * G_AF;       // [3][G_BF]

    const int tid = threadIdx.x, wid = tid >> 5, lane = tid & 31;
    const int gId = lane >> 2, tig = lane & 3;
    const int warp_m = wid & 1;          // 2 warps along M  -> 64 rows each
    const int warp_n = wid >> 1;         // 8 warps along N  -> 32 cols each
    const int rowA0 = blockIdx.y * 128;
    const int rowB0 = blockIdx.x * 256;

    const int r0 = tid >> 3, c4 = (tid & 7) * 4;   // r0: 0..63
    const float* pA0 = g_Xr + (size_t)(rowA0 + r0) * DIN  + c4;
    const float* pG0 = g_G  + (size_t)(rowA0 + r0) * KAUG + c4;
    const float* pW0 = g_Wr + (size_t)(rowB0 + r0) * DIN  + c4;
    const float* pE0 = g_Ber + (size_t)(rowB0 + r0) * RRANK + c4;
    const int sdst = r0 * G_STRD + c4;

    auto load_stage = [&](int kt) {
        const int s = kt % G_NS;
        const int k0 = kt * 32;
        float* dA = Asm + s * G_AF;
        float* dB = Bsm + s * G_BF;
        if (k0 < DIN) {
#pragma unroll
            for (int i = 0; i < 2; i++)
                cpa16(dA + sdst + i * 64 * G_STRD, pA0 + k0 + (size_t)i * 64 * DIN);
#pragma unroll
            for (int i = 0; i < 4; i++)
                cpa16(dB + sdst + i * 64 * G_STRD, pW0 + k0 + (size_t)i * 64 * DIN);
        } else {
            const int kb = k0 - DIN;
            const size_t eoff = (size_t)(kb >> 6) * ((size_t)DOUT * RRANK) + (kb & 63);
#pragma unroll
            for (int i = 0; i < 2; i++)
                cpa16(dA + sdst + i * 64 * G_STRD, pG0 + kb + (size_t)i * 64 * KAUG);
#pragma unroll
            for (int i = 0; i < 4; i++)
                cpa16(dB + sdst + i * 64 * G_STRD, pE0 + eoff + (size_t)i * 64 * RRANK);
        }
        CP_COMMIT();
    };

    float acc[4][4][4];
#pragma unroll
    for (int a = 0; a < 4; a++)
#pragma unroll
        for (int b = 0; b < 4; b++)
#pragma unroll
            for (int q = 0; q < 4; q++) acc[a][b][q] = 0.f;

    load_stage(0); load_stage(1);

    for (int kt = 0; kt < G_KT; kt++) {
        if (kt < G_KT - 1) CP_WAIT(1); else CP_WAIT(0);
        __syncthreads();
        // write buf (kt+2)%3 == (kt-1)%3: drained (all warps passed barrier kt)
        if (kt + 2 < G_KT) load_stage(kt + 2);

        const float* As_ = Asm + (kt % G_NS) * G_AF;
        const float* Bs_ = Bsm + (kt % G_NS) * G_BF;
#pragma unroll
        for (int kk = 0; kk < 4; kk++) {
            const int kc = kk * 8 + tig * 2;   // permuted fragment pair
            float2 afl[4][2]; float2 bfl[4];
#pragma unroll
            for (int mi = 0; mi < 4; mi++) {
                int rm = warp_m * 64 + mi * 16 + gId;
                afl[mi][0] = *(const float2*)&As_[rm * G_STRD + kc];
                afl[mi][1] = *(const float2*)&As_[(rm + 8) * G_STRD + kc];
            }
#pragma unroll
            for (int ni = 0; ni < 4; ni++) {
                int rn = warp_n * 32 + ni * 8 + gId;
                bfl[ni] = *(const float2*)&Bs_[rn * G_STRD + kc];
            }
#pragma unroll
            for (int mi = 0; mi < 4; mi++)
#pragma unroll
                for (int ni = 0; ni < 4; ni++)
                    MMA_TF32(acc[mi][ni][0], acc[mi][ni][1], acc[mi][ni][2], acc[mi][ni][3],
                             __float_as_uint(afl[mi][0].x), __float_as_uint(afl[mi][1].x),
                             __float_as_uint(afl[mi][0].y), __float_as_uint(afl[mi][1].y),
                             __float_as_uint(bfl[ni].x),    __float_as_uint(bfl[ni].y));
        }
    }

    // epilogue: + bias, float2 stores
#pragma unroll
    for (int mi = 0; mi < 4; mi++) {
        int rg = rowA0 + warp_m * 64 + mi * 16 + gId;
#pragma unroll
        for (int ni = 0; ni < 4; ni++) {
            int cg = rowB0 + warp_n * 32 + ni * 8 + tig * 2;
            float2 bv = *(const float2*)&bias[cg];
            *(float2*)&out[(size_t)rg * DOUT + cg] =
                make_float2(acc[mi][ni][0] + bv.x, acc[mi][ni][1] + bv.y);
            *(float2*)&out[(size_t)(rg + 8) * DOUT + cg] =
                make_float2(acc[mi][ni][2] + bv.x, acc[mi][ni][3] + bv.y);
        }
    }
}

// ============================================================================
// launch
// ============================================================================
extern "C" void kernel_launch(void* const* d_in, const int* in_sizes, int n_in,
                              void* d_out, int out_size)
{
    const float* x    = (const float*)d_in[0];
    const float* Wb   = (const float*)d_in[1];
    const float* bias = (const float*)d_in[2];
    const float* A    = (const float*)d_in[3];
    const float* Be   = (const float*)d_in[4];
    const float* Rw   = (const float*)d_in[5];
    float* out = (float*)d_out;

    cudaFuncSetAttribute(k_hl,   cudaFuncAttributeMaxDynamicSharedMemorySize, SMEM_H);
    cudaFuncSetAttribute(k_gemm, cudaFuncAttributeMaxDynamicSharedMemorySize, SMEM_G);

    k_prep<<<2048, 256>>>(x, Wb, Be, A);
    k_hl<<<M_TOK / 64, 256, SMEM_H>>>();
    k_route<<<M_TOK / 32, 256>>>(x, Rw);
    dim3 grid(DOUT / 256, M_TOK / 128);          // (16, 64)
    k_gemm<<<grid, 512, SMEM_G>>>(bias, out);
}